// round 2
// baseline (speedup 1.0000x reference)
#include <cuda_runtime.h>
#include <math.h>

#define NV 16

// ---------------- device scratch ----------------
__device__ float g_pm[240];            // parent_mask [v][p]
__device__ float g_hp[16];             // has_parents per v
__device__ float g_part[240 * 256];    // pair partial sums [pair][block]

// packed f32x2 FMA (Blackwell): d.lo=a.lo*b.lo+c.lo ; d.hi=a.hi*b.hi+c.hi
union F2U { float2 f; unsigned long long u; };
__device__ __forceinline__ float2 ffma2(float2 a, float2 b, float2 c) {
    F2U au, bu, cu, du;
    au.f = a; bu.f = b; cu.f = c;
    asm("fma.rn.f32x2 %0, %1, %2, %3;" : "=l"(du.u) : "l"(au.u), "l"(bu.u), "l"(cu.u));
    return du.f;
}

// ---------------- Kernel A: avg + cov -> corr -> MLP -> adj -> masks ----------------
__global__ void __launch_bounds__(1024) k_adj(
    const float* __restrict__ data,
    const float* __restrict__ Ws1, const float* __restrict__ bs1,
    const float* __restrict__ Ws2, const float* __restrict__ bs2,
    const float* __restrict__ Ws3, const float* __restrict__ bs3,
    float* __restrict__ out_adj)
{
    __shared__ float av[8192];
    __shared__ float scratch[1024];
    __shared__ float cm[16];
    __shared__ float covs[256];
    __shared__ float corr_s[256];
    __shared__ float h1s[256];
    __shared__ float h2s[128];
    __shared__ float adj_s[256];
    __shared__ float pms[240];

    int tid = threadIdx.x;
    // avg over batch (16), vectorized
    for (int t = tid; t < 2048; t += 1024) {
        float4 s = make_float4(0.f, 0.f, 0.f, 0.f);
#pragma unroll
        for (int b = 0; b < 16; b++) {
            float4 v = *(const float4*)(data + b * 8192 + t * 4);
            s.x += v.x; s.y += v.y; s.z += v.z; s.w += v.w;
        }
        s.x *= (1.f/16.f); s.y *= (1.f/16.f); s.z *= (1.f/16.f); s.w *= (1.f/16.f);
        *(float4*)(av + t * 4) = s;
    }
    __syncthreads();

    // column means over SEQ=512
    if (tid < 512) {
        int j = tid & 15, part = tid >> 4;
        float s = 0.f;
        for (int r = 0; r < 16; r++) s += av[(part * 16 + r) * 16 + j];
        scratch[tid] = s;
    }
    __syncthreads();
    if (tid < 16) {
        float s = 0.f;
        for (int part = 0; part < 32; part++) s += scratch[part * 16 + tid];
        cm[tid] = s * (1.f / 512.f);
    }
    __syncthreads();

    // cov
    {
        int pair = tid >> 2, q = tid & 3;
        int i = pair >> 4, j = pair & 15;
        float ci = cm[i], cj = cm[j];
        float s = 0.f;
        for (int r = q * 128; r < q * 128 + 128; r++)
            s += (av[r * 16 + i] - ci) * (av[r * 16 + j] - cj);
        scratch[tid] = s;
    }
    __syncthreads();
    if (tid < 256)
        covs[tid] = scratch[tid*4] + scratch[tid*4+1] + scratch[tid*4+2] + scratch[tid*4+3];
    __syncthreads();
    if (tid < 256) {
        int i = tid >> 4, j = tid & 15;
        float si = sqrtf(fmaxf(covs[i * 16 + i], 0.f));
        float sj = sqrtf(fmaxf(covs[j * 16 + j], 0.f));
        float denom = si * sj;
        float c = denom > 0.f ? covs[tid] / denom : 0.f;
        c = fabsf(c);
        if (i == j) c = 0.f;
        corr_s[tid] = c;
    }
    __syncthreads();

    // L1: (1,256) @ (256,256)
    {
        int o = tid & 255, q = tid >> 8;
        float s = 0.f;
        for (int k = q * 64; k < q * 64 + 64; k++) s = fmaf(corr_s[k], Ws1[k * 256 + o], s);
        scratch[q * 256 + o] = s;
    }
    __syncthreads();
    if (tid < 256)
        h1s[tid] = fmaxf(scratch[tid] + scratch[256 + tid] + scratch[512 + tid] + scratch[768 + tid] + bs1[tid], 0.f);
    __syncthreads();

    // L2
    {
        int o = tid & 127, q = tid >> 7;
        float s = 0.f;
        for (int k = q * 32; k < q * 32 + 32; k++) s = fmaf(h1s[k], Ws2[k * 128 + o], s);
        scratch[q * 128 + o] = s;
    }
    __syncthreads();
    if (tid < 128) {
        float s = bs2[tid];
        for (int q = 0; q < 8; q++) s += scratch[q * 128 + tid];
        h2s[tid] = fmaxf(s, 0.f);
    }
    __syncthreads();

    // L3 -> sigmoid -> triu
    {
        int o = tid & 255, q = tid >> 8;
        float s = 0.f;
        for (int k = q * 32; k < q * 32 + 32; k++) s = fmaf(h2s[k], Ws3[k * 256 + o], s);
        scratch[q * 256 + o] = s;
    }
    __syncthreads();
    if (tid < 256) {
        float logit = scratch[tid] + scratch[256 + tid] + scratch[512 + tid] + scratch[768 + tid] + bs3[tid];
        float a = 1.f / (1.f + expf(-logit));
        int i = tid >> 4, j = tid & 15;
        float val = (j > i) ? a : 0.f;
        adj_s[tid] = val;
        out_adj[tid] = val;
    }
    __syncthreads();
    if (tid < 240) {
        int v = tid / 15, p = tid - v * 15;
        int g = p + (p >= v ? 1 : 0);
        float m = (adj_s[g * 16 + v] > 0.5f) ? 1.f : 0.f;
        pms[tid] = m;
        g_pm[tid] = m;
    }
    __syncthreads();
    if (tid < 16) {
        float s = 0.f;
        for (int p = 0; p < 15; p++) s += pms[tid * 15 + p];
        g_hp[tid] = (s > 0.f) ? 1.f : 0.f;
    }
}

// ---------------- Kernel B: mechanism MLP (FFMA2-packed) ----------------
// grid = (32 chunks, 16 vars), 256 threads (8 warps), warp does 8 samples/iter, 4 iters.
// smem (floats): W1s[1920]@0  b1s[128]@1920  W2t[64*132]@2048  b2s[64]@10496
//                W3s[64]@10560 pms[16]@10624 raw[8w*8s*16]@10640
//                inW2 float2[8w*8s*16]@11664(2048 floats) h1sh[8w*8s*128]@13712
// total 21904 floats = 87616 bytes
__global__ void __launch_bounds__(256, 2) k_mech(
    const float* __restrict__ data,
    const float* __restrict__ Wm1, const float* __restrict__ bm1,
    const float* __restrict__ Wm2, const float* __restrict__ bm2,
    const float* __restrict__ Wm3, const float* __restrict__ bm3,
    float* __restrict__ out_pred)
{
    extern __shared__ float sm[];
    const int v = blockIdx.y;
    float*  W1s  = sm;
    float*  b1s  = sm + 1920;
    float*  W2t  = sm + 2048;
    float*  b2s  = sm + 10496;
    float*  W3s  = sm + 10560;
    float*  pms  = sm + 10624;
    float*  raw  = sm + 10640;
    float2* inW2 = (float2*)(sm + 11664);
    float*  h1sh = sm + 13712;

    int tid = threadIdx.x;
    for (int t = tid; t < 1920; t += 256) W1s[t] = Wm1[v * 1920 + t];
    if (tid < 128) b1s[tid] = bm1[v * 128 + tid];
    for (int t = tid; t < 8192; t += 256) {
        int j = t >> 6, k = t & 63;
        W2t[k * 132 + j] = Wm2[v * 8192 + t];
    }
    if (tid < 64) { b2s[tid] = bm2[v * 64 + tid]; W3s[tid] = Wm3[v * 64 + tid]; }
    if (tid < 15) pms[tid] = g_pm[v * 15 + tid];
    float hp = g_hp[v];
    float b3 = bm3[v];
    __syncthreads();

    int w = tid >> 5, lane = tid & 31;
    float*  rawW = raw  + w * 128;
    float2* inW  = inW2 + w * 128;
    float*  h1W  = h1sh + w * 1024;

    for (int it = 0; it < 4; it++) {
        int base = blockIdx.x * 256 + it * 64 + w * 8;
        // 8 sample rows, coalesced
        {
            int s = lane >> 2, q = lane & 3;
            float4 rv = *(const float4*)(data + (base + s) * 16 + q * 4);
            *(float4*)(rawW + s * 16 + q * 4) = rv;
        }
        __syncwarp();
        // masked, permuted, DUPLICATED inputs (free (x,x) packs)
        for (int t = lane; t < 120; t += 32) {
            int s = t / 15; int p = t - s * 15;
            float val = rawW[s * 16 + p + (p >= v ? 1 : 0)] * pms[p];
            inW[s * 16 + p] = make_float2(val, val);
        }
        __syncwarp();

        // ---- h1: lane owns channels 4L..4L+3 for all 8 samples, packed pairs
        float2 accA[8], accB[8];
        {
            float4 bq = *(float4*)(b1s + lane * 4);
            float2 b01 = make_float2(bq.x, bq.y), b23 = make_float2(bq.z, bq.w);
#pragma unroll
            for (int s = 0; s < 8; s++) { accA[s] = b01; accB[s] = b23; }
        }
#pragma unroll
        for (int p = 0; p < 15; p++) {
            float4 wv = *(float4*)(W1s + p * 128 + lane * 4);
            float2 w01 = make_float2(wv.x, wv.y), w23 = make_float2(wv.z, wv.w);
#pragma unroll
            for (int s = 0; s < 8; s++) {
                float2 xx = inW[s * 16 + p];
                accA[s] = ffma2(w01, xx, accA[s]);
                accB[s] = ffma2(w23, xx, accB[s]);
            }
        }
#pragma unroll
        for (int s = 0; s < 8; s++) {
            float4 r;
            r.x = fmaxf(accA[s].x, 0.f);
            r.y = fmaxf(accA[s].y, 0.f);
            r.z = fmaxf(accB[s].x, 0.f);
            r.w = fmaxf(accB[s].y, 0.f);
            *(float4*)(h1W + s * 128 + lane * 4) = r;   // STS.128, conflict-free
        }
        __syncwarp();

        // ---- h2: lane owns k0=lane, k1=lane+32; packed over j-pairs
        float2 a0[8], a1[8];
        {
            float bk0 = b2s[lane], bk1 = b2s[lane + 32];
#pragma unroll
            for (int s = 0; s < 8; s++) { a0[s] = make_float2(bk0, 0.f); a1[s] = make_float2(bk1, 0.f); }
        }
#pragma unroll 8
        for (int j4 = 0; j4 < 32; j4++) {
            float4 w0 = *(float4*)(W2t + lane * 132 + j4 * 4);
            float4 w1 = *(float4*)(W2t + (lane + 32) * 132 + j4 * 4);
            float2 w0a = make_float2(w0.x, w0.y), w0b = make_float2(w0.z, w0.w);
            float2 w1a = make_float2(w1.x, w1.y), w1b = make_float2(w1.z, w1.w);
#pragma unroll
            for (int s = 0; s < 8; s++) {
                float4 h4 = *(float4*)(h1W + s * 128 + j4 * 4);  // broadcast
                float2 h01 = make_float2(h4.x, h4.y), h23 = make_float2(h4.z, h4.w);
                a0[s] = ffma2(w0a, h01, a0[s]);
                a0[s] = ffma2(w0b, h23, a0[s]);
                a1[s] = ffma2(w1a, h01, a1[s]);
                a1[s] = ffma2(w1b, h23, a1[s]);
            }
        }
        // ---- h3 + warp reduce
        float w3a = W3s[lane], w3b = W3s[lane + 32];
#pragma unroll
        for (int s = 0; s < 8; s++) {
            float h2a = fmaxf(a0[s].x + a0[s].y, 0.f);
            float h2b = fmaxf(a1[s].x + a1[s].y, 0.f);
            float vs = fmaf(h2a, w3a, h2b * w3b);
#pragma unroll
            for (int off = 16; off > 0; off >>= 1)
                vs += __shfl_xor_sync(0xffffffffu, vs, off);
            if (lane == 0) {
                float pred = (hp > 0.f) ? (vs + b3) : rawW[s * 16 + v];
                out_pred[(base + s) * 16 + v] = pred;
            }
        }
        __syncwarp();
    }
}

// ---------------- Kernel C: pair scorer (split-half, FFMA2) ----------------
// 256 blocks x 32 samples; thread pair (2p, 2p+1) handles pair p, 16 channels each.
__global__ void __launch_bounds__(512) k_pairs(
    const float* __restrict__ data,
    const float* __restrict__ Wt1, const float* __restrict__ bt1,
    const float* __restrict__ Wt2, const float* __restrict__ bt2)
{
    __shared__ float2 rows[32 * 16];   // duplicated (x,x)
    int tid = threadIdx.x;
    int sbase = blockIdx.x * 32;
    {
        int s = tid >> 4, j = tid & 15;
        float vv = data[(sbase + s) * 16 + j];
        rows[s * 16 + j] = make_float2(vv, vv);
    }
    __syncthreads();

    int p = tid >> 1, half = tid & 1;
    if (p < 240) {                       // warps 0..14 fully active, warp 15 idle
        int pi = p / 15, r = p - pi * 15;
        int pj = r + (r >= pi ? 1 : 0);
        int co = half * 16;
        float4 w1a[4], w1b[4], bb[4], w2v[4];
#pragma unroll
        for (int q = 0; q < 4; q++) {
            w1a[q] = *(const float4*)(Wt1 + p * 64 + co + q * 4);
            w1b[q] = *(const float4*)(Wt1 + p * 64 + 32 + co + q * 4);
            bb[q]  = *(const float4*)(bt1 + p * 32 + co + q * 4);
            w2v[q] = *(const float4*)(Wt2 + p * 32 + co + q * 4);
        }
        float b2v = bt2[p];
        float accs = 0.f;
        for (int s = 0; s < 32; s++) {
            float2 xi = rows[s * 16 + pi];
            float2 xj = rows[s * 16 + pj];
            float2 sv0 = make_float2(0.f, 0.f), sv1 = make_float2(0.f, 0.f);
#pragma unroll
            for (int q = 0; q < 4; q++) {
                float2 wa01 = make_float2(w1a[q].x, w1a[q].y), wa23 = make_float2(w1a[q].z, w1a[q].w);
                float2 wb01 = make_float2(w1b[q].x, w1b[q].y), wb23 = make_float2(w1b[q].z, w1b[q].w);
                float2 h01 = ffma2(xi, wa01, make_float2(bb[q].x, bb[q].y));
                h01 = ffma2(xj, wb01, h01);
                float2 h23 = ffma2(xi, wa23, make_float2(bb[q].z, bb[q].w));
                h23 = ffma2(xj, wb23, h23);
                h01.x = fmaxf(h01.x, 0.f); h01.y = fmaxf(h01.y, 0.f);
                h23.x = fmaxf(h23.x, 0.f); h23.y = fmaxf(h23.y, 0.f);
                sv0 = ffma2(h01, make_float2(w2v[q].x, w2v[q].y), sv0);
                sv1 = ffma2(h23, make_float2(w2v[q].z, w2v[q].w), sv1);
            }
            float sv = (sv0.x + sv0.y) + (sv1.x + sv1.y);
            float other = __shfl_xor_sync(0xffffffffu, sv, 1);
            if (half == 0) {
                float tot = sv + other + b2v;
                accs += __fdividef(1.f, 1.f + __expf(-tot));
            }
        }
        if (half == 0) g_part[p * 256 + blockIdx.x] = accs;
    }
}

// ---------------- Kernel D: finalize scores ----------------
__global__ void __launch_bounds__(1024) k_fin(float* __restrict__ out_scores) {
    __shared__ float red[960];
    int t = threadIdx.x;
    if (t < 960) {
        int p = t >> 2, q = t & 3;
        float s = 0.f;
        for (int b = q * 64; b < q * 64 + 64; b++) s += g_part[p * 256 + b];
        red[t] = s;
    }
    __syncthreads();
    if (t < 256) {
        int i = t >> 4, j = t & 15;
        float val = 0.f;
        if (i != j) {
            int p = i * 15 + (j > i ? j - 1 : j);
            val = (red[p * 4] + red[p * 4 + 1] + red[p * 4 + 2] + red[p * 4 + 3]) * (1.f / 8192.f);
        }
        out_scores[t] = val;
    }
}

// ---------------- launch ----------------
extern "C" void kernel_launch(void* const* d_in, const int* in_sizes, int n_in,
                              void* d_out, int out_size) {
    const float* data = (const float*)d_in[0];
    const float* Ws1 = (const float*)d_in[1];
    const float* bs1 = (const float*)d_in[2];
    const float* Ws2 = (const float*)d_in[3];
    const float* bs2 = (const float*)d_in[4];
    const float* Ws3 = (const float*)d_in[5];
    const float* bs3 = (const float*)d_in[6];
    const float* Wm1 = (const float*)d_in[7];
    const float* bm1 = (const float*)d_in[8];
    const float* Wm2 = (const float*)d_in[9];
    const float* bm2 = (const float*)d_in[10];
    const float* Wm3 = (const float*)d_in[11];
    const float* bm3 = (const float*)d_in[12];
    const float* Wt1 = (const float*)d_in[13];
    const float* bt1 = (const float*)d_in[14];
    const float* Wt2 = (const float*)d_in[15];
    const float* bt2 = (const float*)d_in[16];

    float* out = (float*)d_out;
    float* out_adj    = out;                 // 256
    float* out_pred   = out + 256;           // 131072
    float* out_scores = out + 256 + 131072;  // 256

    cudaFuncSetAttribute(k_mech, cudaFuncAttributeMaxDynamicSharedMemorySize, 87616);

    k_adj<<<1, 1024>>>(data, Ws1, bs1, Ws2, bs2, Ws3, bs3, out_adj);
    k_mech<<<dim3(32, 16), 256, 87616>>>(data, Wm1, bm1, Wm2, bm2, Wm3, bm3, out_pred);
    k_pairs<<<256, 512>>>(data, Wt1, bt1, Wt2, bt2);
    k_fin<<<1, 1024>>>(out_scores);
}

// round 3
// speedup vs baseline: 1.2963x; 1.2963x over previous
#include <cuda_runtime.h>
#include <math.h>

#define NV 16

// ---------------- device scratch ----------------
__device__ float g_avg[512 * 16];      // mean over batch (SEQ, NV)
__device__ float g_pm[240];            // parent_mask [v][p]
__device__ float g_hp[16];             // has_parents per v
__device__ float g_part[240 * 256];    // pair partial sums [pair][block]

// packed f32x2 FMA
union F2U { float2 f; unsigned long long u; };
__device__ __forceinline__ float2 ffma2(float2 a, float2 b, float2 c) {
    F2U au, bu, cu, du;
    au.f = a; bu.f = b; cu.f = c;
    asm("fma.rn.f32x2 %0, %1, %2, %3;" : "=l"(du.u) : "l"(au.u), "l"(bu.u), "l"(cu.u));
    return du.f;
}

// ---------------- Kernel A1: avg over batch ----------------
__global__ void k_avg(const float* __restrict__ data) {
    int t = blockIdx.x * 64 + threadIdx.x;   // 2048 float4 slots
    float4 s = make_float4(0.f, 0.f, 0.f, 0.f);
#pragma unroll
    for (int b = 0; b < 16; b++) {
        float4 v = *(const float4*)(data + b * 8192 + t * 4);
        s.x += v.x; s.y += v.y; s.z += v.z; s.w += v.w;
    }
    s.x *= (1.f/16.f); s.y *= (1.f/16.f); s.z *= (1.f/16.f); s.w *= (1.f/16.f);
    *(float4*)(g_avg + t * 4) = s;
}

// ---------------- Kernel A2: cov -> corr -> MLP -> adj -> masks ----------------
__global__ void __launch_bounds__(1024) k_adj(
    const float* __restrict__ Ws1, const float* __restrict__ bs1,
    const float* __restrict__ Ws2, const float* __restrict__ bs2,
    const float* __restrict__ Ws3, const float* __restrict__ bs3,
    float* __restrict__ out_adj)
{
    __shared__ float av[8192];
    __shared__ float scratch[1024];
    __shared__ float cm[16];
    __shared__ float covs[256];
    __shared__ float corr_s[256];
    __shared__ float h1s[256];
    __shared__ float h2s[128];
    __shared__ float adj_s[256];
    __shared__ float pms[240];

    int tid = threadIdx.x;
    for (int i = tid; i < 2048; i += 1024)
        *(float4*)(av + i * 4) = *(const float4*)(g_avg + i * 4);
    __syncthreads();

    if (tid < 512) {
        int j = tid & 15, part = tid >> 4;
        float s = 0.f;
        for (int r = 0; r < 16; r++) s += av[(part * 16 + r) * 16 + j];
        scratch[tid] = s;
    }
    __syncthreads();
    if (tid < 16) {
        float s = 0.f;
        for (int part = 0; part < 32; part++) s += scratch[part * 16 + tid];
        cm[tid] = s * (1.f / 512.f);
    }
    __syncthreads();

    {
        int pair = tid >> 2, q = tid & 3;
        int i = pair >> 4, j = pair & 15;
        float ci = cm[i], cj = cm[j];
        float s = 0.f;
        for (int r = q * 128; r < q * 128 + 128; r++)
            s += (av[r * 16 + i] - ci) * (av[r * 16 + j] - cj);
        scratch[tid] = s;
    }
    __syncthreads();
    if (tid < 256)
        covs[tid] = scratch[tid*4] + scratch[tid*4+1] + scratch[tid*4+2] + scratch[tid*4+3];
    __syncthreads();
    if (tid < 256) {
        int i = tid >> 4, j = tid & 15;
        float si = sqrtf(fmaxf(covs[i * 16 + i], 0.f));
        float sj = sqrtf(fmaxf(covs[j * 16 + j], 0.f));
        float denom = si * sj;
        float c = denom > 0.f ? covs[tid] / denom : 0.f;
        c = fabsf(c);
        if (i == j) c = 0.f;
        corr_s[tid] = c;
    }
    __syncthreads();

    {
        int o = tid & 255, q = tid >> 8;
        float s = 0.f;
        for (int k = q * 64; k < q * 64 + 64; k++) s = fmaf(corr_s[k], Ws1[k * 256 + o], s);
        scratch[q * 256 + o] = s;
    }
    __syncthreads();
    if (tid < 256)
        h1s[tid] = fmaxf(scratch[tid] + scratch[256 + tid] + scratch[512 + tid] + scratch[768 + tid] + bs1[tid], 0.f);
    __syncthreads();

    {
        int o = tid & 127, q = tid >> 7;
        float s = 0.f;
        for (int k = q * 32; k < q * 32 + 32; k++) s = fmaf(h1s[k], Ws2[k * 128 + o], s);
        scratch[q * 128 + o] = s;
    }
    __syncthreads();
    if (tid < 128) {
        float s = bs2[tid];
        for (int q = 0; q < 8; q++) s += scratch[q * 128 + tid];
        h2s[tid] = fmaxf(s, 0.f);
    }
    __syncthreads();

    {
        int o = tid & 255, q = tid >> 8;
        float s = 0.f;
        for (int k = q * 32; k < q * 32 + 32; k++) s = fmaf(h2s[k], Ws3[k * 256 + o], s);
        scratch[q * 256 + o] = s;
    }
    __syncthreads();
    if (tid < 256) {
        float logit = scratch[tid] + scratch[256 + tid] + scratch[512 + tid] + scratch[768 + tid] + bs3[tid];
        float a = 1.f / (1.f + expf(-logit));
        int i = tid >> 4, j = tid & 15;
        float val = (j > i) ? a : 0.f;
        adj_s[tid] = val;
        out_adj[tid] = val;
    }
    __syncthreads();
    if (tid < 240) {
        int v = tid / 15, p = tid - v * 15;
        int g = p + (p >= v ? 1 : 0);
        float m = (adj_s[g * 16 + v] > 0.5f) ? 1.f : 0.f;
        pms[tid] = m;
        g_pm[tid] = m;
    }
    __syncthreads();
    if (tid < 16) {
        float s = 0.f;
        for (int p = 0; p < 15; p++) s += pms[tid * 15 + p];
        g_hp[tid] = (s > 0.f) ? 1.f : 0.f;
    }
}

// ---------------- Kernel B: mechanism MLP (FFMA2, broadcast-load h2) ----------------
// grid (32,16), 256 threads (8 warps), warp does 8 samples/iter, 4 iters.
// smem floats: W1s[1920]@0 b1s[128]@1920 W2s[8192]@2048 ([j][k] natural)
//   b2s[64]@10240 W3s[64]@10304 pms[16]@10368 raw[1024]@10384
//   inW2 float2[1024]@11408 (2048 floats) h1sh[8192]@13456
// total 21648 floats = 86592 B  -> 2 blocks/SM
__global__ void __launch_bounds__(256, 2) k_mech(
    const float* __restrict__ data,
    const float* __restrict__ Wm1, const float* __restrict__ bm1,
    const float* __restrict__ Wm2, const float* __restrict__ bm2,
    const float* __restrict__ Wm3, const float* __restrict__ bm3,
    float* __restrict__ out_pred)
{
    extern __shared__ float sm[];
    const int v = blockIdx.y;
    float*  W1s  = sm;
    float*  b1s  = sm + 1920;
    float*  W2s  = sm + 2048;
    float*  b2s  = sm + 10240;
    float*  W3s  = sm + 10304;
    float*  pms  = sm + 10368;
    float*  raw  = sm + 10384;
    float2* inW2 = (float2*)(sm + 11408);
    float*  h1sh = sm + 13456;

    int tid = threadIdx.x;
    for (int t = tid; t < 1920; t += 256) W1s[t] = Wm1[v * 1920 + t];
    if (tid < 128) b1s[tid] = bm1[v * 128 + tid];
    for (int t = tid; t < 2048; t += 256)   // straight copy, [j][k]
        *(float4*)(W2s + t * 4) = *(const float4*)(Wm2 + v * 8192 + t * 4);
    if (tid < 64) { b2s[tid] = bm2[v * 64 + tid]; W3s[tid] = Wm3[v * 64 + tid]; }
    if (tid < 15) pms[tid] = g_pm[v * 15 + tid];
    float hp = g_hp[v];
    float b3 = bm3[v];
    __syncthreads();

    int w = tid >> 5, lane = tid & 31;
    int kg = lane >> 1, sg = lane & 1;
    float*  rawW = raw  + w * 128;
    float2* inW  = inW2 + w * 128;
    float*  h1W  = h1sh + w * 1024;
    float*  h1base = h1W + sg * 4 * 128;

    for (int it = 0; it < 4; it++) {
        int base = blockIdx.x * 256 + it * 64 + w * 8;
        {   // 8 sample rows, coalesced
            int s = lane >> 2, q = lane & 3;
            float4 rv = *(const float4*)(data + (base + s) * 16 + q * 4);
            *(float4*)(rawW + s * 16 + q * 4) = rv;
        }
        __syncwarp();
        for (int t = lane; t < 120; t += 32) {
            int s = t / 15; int p = t - s * 15;
            float val = rawW[s * 16 + p + (p >= v ? 1 : 0)] * pms[p];
            inW[s * 16 + p] = make_float2(val, val);
        }
        __syncwarp();

        // ---- h1: lane owns channels 4L..4L+3, all 8 samples
        float2 accA[8], accB[8];
        {
            float4 bq = *(float4*)(b1s + lane * 4);
            float2 b01 = make_float2(bq.x, bq.y), b23 = make_float2(bq.z, bq.w);
#pragma unroll
            for (int s = 0; s < 8; s++) { accA[s] = b01; accB[s] = b23; }
        }
#pragma unroll
        for (int p = 0; p < 15; p++) {
            float4 wv = *(float4*)(W1s + p * 128 + lane * 4);
            float2 w01 = make_float2(wv.x, wv.y), w23 = make_float2(wv.z, wv.w);
#pragma unroll
            for (int s = 0; s < 8; s++) {
                float2 xx = inW[s * 16 + p];
                accA[s] = ffma2(w01, xx, accA[s]);
                accB[s] = ffma2(w23, xx, accB[s]);
            }
        }
#pragma unroll
        for (int s = 0; s < 8; s++) {
            float4 r;
            r.x = fmaxf(accA[s].x, 0.f);
            r.y = fmaxf(accA[s].y, 0.f);
            r.z = fmaxf(accB[s].x, 0.f);
            r.w = fmaxf(accB[s].y, 0.f);
            *(float4*)(h1W + s * 128 + lane * 4) = r;
        }
        __syncwarp();

        // ---- h2: lane (kg,sg) owns k=4kg..4kg+3, samples sg*4..sg*4+3
        float2 a0[4], a1[4];
        {
            float4 bq = *(float4*)(b2s + kg * 4);
#pragma unroll
            for (int si = 0; si < 4; si++) {
                a0[si] = make_float2(bq.x, bq.y);
                a1[si] = make_float2(bq.z, bq.w);
            }
        }
#pragma unroll 2
        for (int j4 = 0; j4 < 32; j4++) {
            float4 w0 = *(float4*)(W2s + (j4 * 4 + 0) * 64 + kg * 4);
            float4 w1 = *(float4*)(W2s + (j4 * 4 + 1) * 64 + kg * 4);
            float4 w2 = *(float4*)(W2s + (j4 * 4 + 2) * 64 + kg * 4);
            float4 w3 = *(float4*)(W2s + (j4 * 4 + 3) * 64 + kg * 4);
#pragma unroll
            for (int si = 0; si < 4; si++) {
                float4 h4 = *(float4*)(h1base + si * 128 + j4 * 4);  // broadcast
                float2 hx = make_float2(h4.x, h4.x);
                float2 hy = make_float2(h4.y, h4.y);
                float2 hz = make_float2(h4.z, h4.z);
                float2 hw = make_float2(h4.w, h4.w);
                a0[si] = ffma2(make_float2(w0.x, w0.y), hx, a0[si]);
                a1[si] = ffma2(make_float2(w0.z, w0.w), hx, a1[si]);
                a0[si] = ffma2(make_float2(w1.x, w1.y), hy, a0[si]);
                a1[si] = ffma2(make_float2(w1.z, w1.w), hy, a1[si]);
                a0[si] = ffma2(make_float2(w2.x, w2.y), hz, a0[si]);
                a1[si] = ffma2(make_float2(w2.z, w2.w), hz, a1[si]);
                a0[si] = ffma2(make_float2(w3.x, w3.y), hw, a0[si]);
                a1[si] = ffma2(make_float2(w3.z, w3.w), hw, a1[si]);
            }
        }

        // ---- h3: relu + dot W3[4kg..3], reduce over kg (xor 2,4,8,16)
        float4 w3v = *(float4*)(W3s + kg * 4);
        float part[4];
#pragma unroll
        for (int si = 0; si < 4; si++) {
            float t0 = fmaf(fmaxf(a0[si].x, 0.f), w3v.x, fmaxf(a0[si].y, 0.f) * w3v.y);
            float t1 = fmaf(fmaxf(a1[si].x, 0.f), w3v.z, fmaxf(a1[si].y, 0.f) * w3v.w);
            part[si] = t0 + t1;
        }
#pragma unroll
        for (int off = 2; off < 32; off <<= 1) {
#pragma unroll
            for (int si = 0; si < 4; si++)
                part[si] += __shfl_xor_sync(0xffffffffu, part[si], off);
        }
        if (lane < 2) {
#pragma unroll
            for (int si = 0; si < 4; si++) {
                int s = lane * 4 + si;
                float pred = (hp > 0.f) ? (part[si] + b3) : rawW[s * 16 + v];
                out_pred[(base + s) * 16 + v] = pred;
            }
        }
        __syncwarp();
    }
}

// ---------------- Kernel C: pair scorer (split-half, FFMA2) ----------------
__global__ void __launch_bounds__(512) k_pairs(
    const float* __restrict__ data,
    const float* __restrict__ Wt1, const float* __restrict__ bt1,
    const float* __restrict__ Wt2, const float* __restrict__ bt2)
{
    __shared__ float2 rows[32 * 16];
    int tid = threadIdx.x;
    int sbase = blockIdx.x * 32;
    {
        int s = tid >> 4, j = tid & 15;
        float vv = data[(sbase + s) * 16 + j];
        rows[s * 16 + j] = make_float2(vv, vv);
    }
    __syncthreads();

    int p = tid >> 1, half = tid & 1;
    if (p < 240) {
        int pi = p / 15, r = p - pi * 15;
        int pj = r + (r >= pi ? 1 : 0);
        int co = half * 16;
        float4 w1a[4], w1b[4], bb[4], w2v[4];
#pragma unroll
        for (int q = 0; q < 4; q++) {
            w1a[q] = *(const float4*)(Wt1 + p * 64 + co + q * 4);
            w1b[q] = *(const float4*)(Wt1 + p * 64 + 32 + co + q * 4);
            bb[q]  = *(const float4*)(bt1 + p * 32 + co + q * 4);
            w2v[q] = *(const float4*)(Wt2 + p * 32 + co + q * 4);
        }
        float b2v = bt2[p];
        float accs = 0.f;
        for (int s = 0; s < 32; s++) {
            float2 xi = rows[s * 16 + pi];
            float2 xj = rows[s * 16 + pj];
            float2 sv0 = make_float2(0.f, 0.f), sv1 = make_float2(0.f, 0.f);
#pragma unroll
            for (int q = 0; q < 4; q++) {
                float2 h01 = ffma2(xi, make_float2(w1a[q].x, w1a[q].y), make_float2(bb[q].x, bb[q].y));
                h01 = ffma2(xj, make_float2(w1b[q].x, w1b[q].y), h01);
                float2 h23 = ffma2(xi, make_float2(w1a[q].z, w1a[q].w), make_float2(bb[q].z, bb[q].w));
                h23 = ffma2(xj, make_float2(w1b[q].z, w1b[q].w), h23);
                h01.x = fmaxf(h01.x, 0.f); h01.y = fmaxf(h01.y, 0.f);
                h23.x = fmaxf(h23.x, 0.f); h23.y = fmaxf(h23.y, 0.f);
                sv0 = ffma2(h01, make_float2(w2v[q].x, w2v[q].y), sv0);
                sv1 = ffma2(h23, make_float2(w2v[q].z, w2v[q].w), sv1);
            }
            float sv = (sv0.x + sv0.y) + (sv1.x + sv1.y);
            float other = __shfl_xor_sync(0xffffffffu, sv, 1);
            if (half == 0) {
                float tot = sv + other + b2v;
                accs += __fdividef(1.f, 1.f + __expf(-tot));
            }
        }
        if (half == 0) g_part[p * 256 + blockIdx.x] = accs;
    }
}

// ---------------- Kernel D: finalize (warp per pair, coalesced) ----------------
__global__ void __launch_bounds__(256) k_fin(float* __restrict__ out_scores) {
    int w = threadIdx.x >> 5, lane = threadIdx.x & 31;
    int p = blockIdx.x * 8 + w;     // 30 blocks * 8 warps = 240 pairs
    float s = 0.f;
#pragma unroll
    for (int i = 0; i < 8; i++) s += g_part[p * 256 + i * 32 + lane];
#pragma unroll
    for (int off = 16; off > 0; off >>= 1)
        s += __shfl_xor_sync(0xffffffffu, s, off);
    if (lane == 0) {
        int pi = p / 15, r = p - pi * 15;
        int pj = r + (r >= pi ? 1 : 0);
        out_scores[pi * 16 + pj] = s * (1.f / 8192.f);
    }
    if (blockIdx.x == 0 && w == 0 && lane < 16) out_scores[lane * 17] = 0.f;
}

// ---------------- launch ----------------
extern "C" void kernel_launch(void* const* d_in, const int* in_sizes, int n_in,
                              void* d_out, int out_size) {
    const float* data = (const float*)d_in[0];
    const float* Ws1 = (const float*)d_in[1];
    const float* bs1 = (const float*)d_in[2];
    const float* Ws2 = (const float*)d_in[3];
    const float* bs2 = (const float*)d_in[4];
    const float* Ws3 = (const float*)d_in[5];
    const float* bs3 = (const float*)d_in[6];
    const float* Wm1 = (const float*)d_in[7];
    const float* bm1 = (const float*)d_in[8];
    const float* Wm2 = (const float*)d_in[9];
    const float* bm2 = (const float*)d_in[10];
    const float* Wm3 = (const float*)d_in[11];
    const float* bm3 = (const float*)d_in[12];
    const float* Wt1 = (const float*)d_in[13];
    const float* bt1 = (const float*)d_in[14];
    const float* Wt2 = (const float*)d_in[15];
    const float* bt2 = (const float*)d_in[16];

    float* out = (float*)d_out;
    float* out_adj    = out;
    float* out_pred   = out + 256;
    float* out_scores = out + 256 + 131072;

    cudaFuncSetAttribute(k_mech, cudaFuncAttributeMaxDynamicSharedMemorySize, 86592);

    k_avg<<<32, 64>>>(data);
    k_adj<<<1, 1024>>>(Ws1, bs1, Ws2, bs2, Ws3, bs3, out_adj);
    k_mech<<<dim3(32, 16), 256, 86592>>>(data, Wm1, bm1, Wm2, bm2, Wm3, bm3, out_pred);
    k_pairs<<<256, 512>>>(data, Wt1, bt1, Wt2, bt2);
    k_fin<<<30, 256>>>(out_scores);
}